// round 2
// baseline (speedup 1.0000x reference)
#include <cuda_runtime.h>
#include <math.h>

// ---------------------------------------------------------------------------
// CenterHead: shared conv3x3(512->64)+BN+ReLU, 6x [conv3x3(64->64)+BN+ReLU,
// conv3x3(64->3)+bias], concat selected channels, plus gaussian target assign.
// fp32 direct conv, 8oc x 8px register micro-tile per thread.
// Hidden buffer reused across heads (sequential in-stream) to cap scratch.
// ---------------------------------------------------------------------------

#define HH 188
#define WW 188
#define HW (188*188)
#define BB 4
#define MM 200
#define NMAX 500

// output region offsets (float32 elements)
#define OFF_HEAD 0
#define OFF_HM   (4*12*HW)             // 1,696,512
#define OFF_TB   (OFF_HM + 4*3*HW)     // 2,120,640
#define OFF_IND  (OFF_TB + 4*NMAX*8)   // 2,136,640
#define OFF_MASK (OFF_IND + 4*NMAX)    // 2,138,640
#define OUT_TOTAL (OFF_MASK + 4*NMAX)  // 2,140,640

// scratch (static device arrays: allocation-free contract) ~72 MB total
__device__ float g_shared_feat[4 * 64 * HW];   // [b][oc][h][w]
__device__ float g_h[4 * 64 * HW];             // per-head hidden, reused

// ---------------------------------------------------------------------------
// conv3x3 + BN + ReLU.  Block = 256 threads, computes 16x16 spatial x 64 oc.
// Thread = 8 oc x 8 px (one half-row).  Cin chunked by 8 through smem.
// MULTI=false: in=gin (Cin=512), out=g_shared_feat, head=0, grid.z=b
// MULTI=true : in=g_shared_feat (Cin=64), out=g_h, weights at `head`
// ---------------------------------------------------------------------------
template<int CIN, bool MULTI>
__global__ __launch_bounds__(256, 2)
void conv_bn_relu(const float* __restrict__ gin,
                  const float* __restrict__ wt,
                  const float* __restrict__ bn,
                  int head)
{
    const int b = blockIdx.z;

    const float* img  = (MULTI ? g_shared_feat : gin) + (size_t)b * CIN * HW;
    float*       outp = (MULTI ? g_h : g_shared_feat) + (size_t)b * 64 * HW;
    const float* w    = wt + (size_t)head * 64 * CIN * 9;
    const float* bnp  = bn + head * 256;

    __shared__ float sIn[8][18][21];   // [ic][row][col] pad 21: conflict-limited
    __shared__ float sW[72][64];       // [ic*9+k][oc]

    const int tid  = threadIdx.x;
    const int ocg  = tid >> 5;            // 0..7  (oc group of 8)
    const int pg   = tid & 31;            // 0..31 (pixel group)
    const int prow = pg >> 1;             // 0..15
    const int pcol = (pg & 1) << 3;       // 0 or 8

    const int ty0 = blockIdx.y * 16;
    const int tx0 = blockIdx.x * 16;

    float acc[8][8];
#pragma unroll
    for (int o = 0; o < 8; ++o)
#pragma unroll
        for (int j = 0; j < 8; ++j) acc[o][j] = 0.f;

    for (int ic0 = 0; ic0 < CIN; ic0 += 8) {
        __syncthreads();  // previous chunk compute done before overwriting smem
        // load input tile 8 x 18 x 18
        for (int e = tid; e < 8 * 18 * 18; e += 256) {
            int ic = e / 324;
            int r  = (e % 324) / 18;
            int c  = e % 18;
            int gy = ty0 - 1 + r;
            int gx = tx0 - 1 + c;
            float v = 0.f;
            if ((unsigned)gy < HH && (unsigned)gx < WW)
                v = img[(size_t)(ic0 + ic) * HW + gy * WW + gx];
            sIn[ic][r][c] = v;
        }
        // load weights 72 x 64
        for (int e = tid; e < 72 * 64; e += 256) {
            int oc  = e & 63;
            int ick = e >> 6;
            sW[ick][oc] = w[(size_t)oc * CIN * 9 + ic0 * 9 + ick];
        }
        __syncthreads();

#pragma unroll 1
        for (int ic = 0; ic < 8; ++ic) {
#pragma unroll
            for (int k = 0; k < 9; ++k) {
                const int ky = k / 3, kx = k % 3;
                float wreg[8], ireg[8];
#pragma unroll
                for (int o = 0; o < 8; ++o) wreg[o] = sW[ic * 9 + k][ocg * 8 + o];
#pragma unroll
                for (int j = 0; j < 8; ++j) ireg[j] = sIn[ic][prow + ky][pcol + kx + j];
#pragma unroll
                for (int o = 0; o < 8; ++o)
#pragma unroll
                    for (int j = 0; j < 8; ++j)
                        acc[o][j] = fmaf(wreg[o], ireg[j], acc[o][j]);
            }
        }
    }

    // BN (inference) + ReLU epilogue
    const int y = ty0 + prow;
    if (y < HH) {
#pragma unroll
        for (int o = 0; o < 8; ++o) {
            const int oc = ocg * 8 + o;
            const float gamma = bnp[oc];
            const float beta  = bnp[64 + oc];
            const float mean  = bnp[128 + oc];
            const float var   = bnp[192 + oc];
            const float scale = gamma * rsqrtf(var + 1e-5f);
            float* orow = outp + (size_t)oc * HW + (size_t)y * WW;
#pragma unroll
            for (int j = 0; j < 8; ++j) {
                const int x = tx0 + pcol + j;
                if (x < WW) {
                    float v = (acc[o][j] - mean) * scale + beta;
                    orow[x] = fmaxf(v, 0.f);
                }
            }
        }
    }
}

// ---------------------------------------------------------------------------
// conv3x3 (64 -> 3) + bias, channel-select concat into head_out region.
// Block 256 = 16x16 pixels, 3 accumulators/thread. grid.z = b.
// ---------------------------------------------------------------------------
__global__ __launch_bounds__(256)
void conv2_kernel(const float* __restrict__ w2,
                  const float* __restrict__ b2,
                  float* __restrict__ out,
                  int head)
{
    const int b = blockIdx.z;
    const float* img = g_h + (size_t)b * 64 * HW;

    __shared__ float sW2[3 * 64 * 9];   // 1728
    __shared__ float sIn[8][18][21];

    const int tid = threadIdx.x;
    for (int e = tid; e < 1728; e += 256)
        sW2[e] = w2[(size_t)head * 1728 + e];

    const int ry = tid >> 4;
    const int rx = tid & 15;
    const int ty0 = blockIdx.y * 16;
    const int tx0 = blockIdx.x * 16;

    float a0 = 0.f, a1 = 0.f, a2 = 0.f;

    for (int ic0 = 0; ic0 < 64; ic0 += 8) {
        __syncthreads();
        for (int e = tid; e < 8 * 18 * 18; e += 256) {
            int ic = e / 324;
            int r  = (e % 324) / 18;
            int c  = e % 18;
            int gy = ty0 - 1 + r;
            int gx = tx0 - 1 + c;
            float v = 0.f;
            if ((unsigned)gy < HH && (unsigned)gx < WW)
                v = img[(size_t)(ic0 + ic) * HW + gy * WW + gx];
            sIn[ic][r][c] = v;
        }
        __syncthreads();

#pragma unroll 1
        for (int ic = 0; ic < 8; ++ic) {
#pragma unroll
            for (int k = 0; k < 9; ++k) {
                const int ky = k / 3, kx = k % 3;
                const float iv = sIn[ic][ry + ky][rx + kx];
                const int wb = (ic0 + ic) * 9 + k;
                a0 = fmaf(sW2[wb], iv, a0);
                a1 = fmaf(sW2[576 + wb], iv, a1);
                a2 = fmaf(sW2[1152 + wb], iv, a2);
            }
        }
    }

    const int y = ty0 + ry;
    const int x = tx0 + rx;
    if (y < HH && x < WW) {
        float av[3];
        av[0] = a0 + b2[head * 3 + 0];
        av[1] = a1 + b2[head * 3 + 1];
        av[2] = a2 + b2[head * 3 + 2];
        const int offc[6] = {0, 2, 3, 6, 8, 9};
        const int nch[6]  = {2, 1, 3, 2, 1, 3};
        for (int o = 0; o < nch[head]; ++o)
            out[OFF_HEAD + ((size_t)b * 12 + offc[head] + o) * HW + (size_t)y * WW + x] = av[o];
    }
}

// ---------------------------------------------------------------------------
// zero heatmap + target_boxes + inds + mask regions
// ---------------------------------------------------------------------------
__global__ void zero_tail_kernel(float* __restrict__ out)
{
    const int n = OUT_TOTAL - OFF_HM;
    int i = blockIdx.x * blockDim.x + threadIdx.x;
    if (i < n) out[OFF_HM + i] = 0.f;
}

// ---------------------------------------------------------------------------
// target assignment: one thread per (b, m) gt box.
// ---------------------------------------------------------------------------
__global__ void assign_kernel(const float* __restrict__ gt, float* __restrict__ out)
{
    const int t = blockIdx.x * blockDim.x + threadIdx.x;
    if (t >= BB * MM) return;
    const int b = t / MM;
    const int m = t % MM;
    const float* gb = gt + (size_t)(b * MM + m) * 8;

    const float x  = gb[0], y  = gb[1], zc = gb[2];
    const float dx = gb[3], dy = gb[4], dz = gb[5];
    const float hd = gb[6];
    const int   cls = (int)gb[7];

    const bool valid = (dx > 0.f) && (dy > 0.f);
    const float vf = valid ? 1.f : 0.f;

    float cx = (x - (-75.2f)) / 0.1f / 8.0f;
    cx = fminf(fmaxf(cx, 0.f), (float)WW - 0.5f);
    float cy = (y - (-75.2f)) / 0.1f / 8.0f;
    cy = fminf(fmaxf(cy, 0.f), (float)HH - 0.5f);
    const int cxi = (int)floorf(cx);
    const int cyi = (int)floorf(cy);

    const float dxp = dx / 0.1f / 8.0f;
    const float dyp = dy / 0.1f / 8.0f;

    // gaussian_radius(height=dxp, width=dyp, overlap=0.1)
    const float ov = 0.1f;
    const float hgt = dxp, wdt = dyp;
    const float b1 = hgt + wdt;
    const float c1 = wdt * hgt * (1.f - ov) / (1.f + ov);
    const float sq1 = sqrtf(fmaxf(b1 * b1 - 4.f * c1, 0.f));
    const float r1 = (b1 + sq1) * 0.5f;
    const float b2v = 2.f * (hgt + wdt);
    const float c2 = (1.f - ov) * wdt * hgt;
    const float sq2 = sqrtf(fmaxf(b2v * b2v - 16.f * c2, 0.f));
    const float r2 = (b2v + sq2) * 0.5f;
    const float a3 = 4.f * ov;
    const float b3 = -2.f * ov * (hgt + wdt);
    const float c3 = (ov - 1.f) * wdt * hgt;
    const float sq3 = sqrtf(fmaxf(b3 * b3 - 4.f * a3 * c3, 0.f));
    const float r3 = (b3 + sq3) * 0.5f;

    float r = fminf(fminf(r1, r2), r3);
    r = fmaxf(floorf(r), 2.0f);
    const float sigma = (2.f * r + 1.f) / 6.f;
    const float inv2s2 = 1.f / (2.f * sigma * sigma);

    // target_boxes / inds / mask
    float* tb = out + OFF_TB + (size_t)(b * NMAX + m) * 8;
    tb[0] = (cx - (float)cxi) * vf;
    tb[1] = (cy - (float)cyi) * vf;
    tb[2] = zc * vf;
    tb[3] = logf(dx) * vf;
    tb[4] = logf(dy) * vf;
    tb[5] = logf(dz) * vf;
    tb[6] = cosf(hd) * vf;
    tb[7] = sinf(hd) * vf;
    out[OFF_IND + b * NMAX + m]  = (float)((cyi * WW + cxi) * (valid ? 1 : 0));
    out[OFF_MASK + b * NMAX + m] = vf;

    if (!valid || cls < 1 || cls > 3) return;

    // gaussian max-splat into heatmap channel (cls-1)
    float* hm = out + OFF_HM + ((size_t)(b * 3 + (cls - 1))) * HW;
    const int ir = (int)r;
    for (int oy = -ir; oy <= ir; ++oy) {
        const int py = cyi + oy;
        if ((unsigned)py >= HH) continue;
        for (int ox = -ir; ox <= ir; ++ox) {
            const int px = cxi + ox;
            if ((unsigned)px >= WW) continue;
            const float g = expf(-(float)(oy * oy + ox * ox) * inv2s2);
            atomicMax((int*)&hm[(size_t)py * WW + px], __float_as_int(g));
        }
    }
}

// ---------------------------------------------------------------------------
extern "C" void kernel_launch(void* const* d_in, const int* in_sizes, int n_in,
                              void* d_out, int out_size)
{
    const float* sf       = (const float*)d_in[0];  // spatial_features [4,512,188,188]
    const float* gt       = (const float*)d_in[1];  // gt_boxes [4,200,8]
    const float* w_shared = (const float*)d_in[2];  // [64,512,3,3]
    const float* bn_sh    = (const float*)d_in[3];  // [4,64]
    const float* w1       = (const float*)d_in[4];  // [6,64,64,3,3]
    const float* bnh      = (const float*)d_in[5];  // [6,4,64]
    const float* w2       = (const float*)d_in[6];  // [6,3,64,3,3]
    const float* b2       = (const float*)d_in[7];  // [6,3]
    float* out = (float*)d_out;

    (void)in_sizes; (void)n_in; (void)out_size;

    // zero heatmap/targets, then splat (ordering via default stream)
    {
        const int n = OUT_TOTAL - OFF_HM;
        zero_tail_kernel<<<(n + 255) / 256, 256>>>(out);
    }
    assign_kernel<<<(BB * MM + 255) / 256, 256>>>(gt, out);

    // shared conv 512 -> 64 (+BN+ReLU)
    conv_bn_relu<512, false><<<dim3(12, 12, 4), 256>>>(sf, w_shared, bn_sh, 0);

    // per head: conv1 64 -> 64 (+BN+ReLU) into reused g_h, then conv2 64 -> 3
    for (int head = 0; head < 6; ++head) {
        conv_bn_relu<64, true><<<dim3(12, 12, 4), 256>>>(nullptr, w1, bnh, head);
        conv2_kernel<<<dim3(12, 12, 4), 256>>>(w2, b2, out, head);
    }
}

// round 3
// speedup vs baseline: 1.0022x; 1.0022x over previous
#include <cuda_runtime.h>
#include <math.h>

// ---------------------------------------------------------------------------
// CenterHead: shared conv3x3(512->64)+BN+ReLU, 6x [conv3x3(64->64)+BN+ReLU,
// conv3x3(64->3)+bias], concat selected channels, plus gaussian target assign.
// fp32 direct conv, 8oc x 8px register micro-tile per thread.
// Hidden buffer reused across heads (sequential in-stream) to cap scratch.
// ---------------------------------------------------------------------------

#define HH 188
#define WW 188
#define HW (188*188)
#define BB 4
#define MM 200
#define NMAX 500

// output region offsets (float32 elements)
#define OFF_HEAD 0
#define OFF_HM   (4*12*HW)             // 1,696,512
#define OFF_TB   (OFF_HM + 4*3*HW)     // 2,120,640
#define OFF_IND  (OFF_TB + 4*NMAX*8)   // 2,136,640
#define OFF_MASK (OFF_IND + 4*NMAX)    // 2,138,640
#define OUT_TOTAL (OFF_MASK + 4*NMAX)  // 2,140,640

// scratch (static device arrays: allocation-free contract) ~72 MB total
__device__ float g_shared_feat[4 * 64 * HW];   // [b][oc][h][w]
__device__ float g_h[4 * 64 * HW];             // per-head hidden, reused

// ---------------------------------------------------------------------------
// conv3x3 + BN + ReLU.  Block = 256 threads, computes 16x16 spatial x 64 oc.
// Thread = 8 oc x 8 px (one half-row).  Cin chunked by 8 through smem.
// MULTI=false: in=gin (Cin=512), out=g_shared_feat, head=0, grid.z=b
// MULTI=true : in=g_shared_feat (Cin=64), out=g_h, weights at `head`
// ---------------------------------------------------------------------------
template<int CIN, bool MULTI>
__global__ __launch_bounds__(256, 2)
void conv_bn_relu(const float* __restrict__ gin,
                  const float* __restrict__ wt,
                  const float* __restrict__ bn,
                  int head)
{
    const int b = blockIdx.z;

    const float* img  = (MULTI ? g_shared_feat : gin) + (size_t)b * CIN * HW;
    float*       outp = (MULTI ? g_h : g_shared_feat) + (size_t)b * 64 * HW;
    const float* w    = wt + (size_t)head * 64 * CIN * 9;
    const float* bnp  = bn + head * 256;

    __shared__ float sIn[8][18][21];   // [ic][row][col] pad 21: conflict-limited
    __shared__ float sW[72][64];       // [ic*9+k][oc]

    const int tid  = threadIdx.x;
    const int ocg  = tid >> 5;            // 0..7  (oc group of 8)
    const int pg   = tid & 31;            // 0..31 (pixel group)
    const int prow = pg >> 1;             // 0..15
    const int pcol = (pg & 1) << 3;       // 0 or 8

    const int ty0 = blockIdx.y * 16;
    const int tx0 = blockIdx.x * 16;

    float acc[8][8];
#pragma unroll
    for (int o = 0; o < 8; ++o)
#pragma unroll
        for (int j = 0; j < 8; ++j) acc[o][j] = 0.f;

    for (int ic0 = 0; ic0 < CIN; ic0 += 8) {
        __syncthreads();  // previous chunk compute done before overwriting smem
        // load input tile 8 x 18 x 18
        for (int e = tid; e < 8 * 18 * 18; e += 256) {
            int ic = e / 324;
            int r  = (e % 324) / 18;
            int c  = e % 18;
            int gy = ty0 - 1 + r;
            int gx = tx0 - 1 + c;
            float v = 0.f;
            if ((unsigned)gy < HH && (unsigned)gx < WW)
                v = img[(size_t)(ic0 + ic) * HW + gy * WW + gx];
            sIn[ic][r][c] = v;
        }
        // load weights 72 x 64
        for (int e = tid; e < 72 * 64; e += 256) {
            int oc  = e & 63;
            int ick = e >> 6;
            sW[ick][oc] = w[(size_t)oc * CIN * 9 + ic0 * 9 + ick];
        }
        __syncthreads();

#pragma unroll 1
        for (int ic = 0; ic < 8; ++ic) {
#pragma unroll
            for (int k = 0; k < 9; ++k) {
                const int ky = k / 3, kx = k % 3;
                float wreg[8], ireg[8];
#pragma unroll
                for (int o = 0; o < 8; ++o) wreg[o] = sW[ic * 9 + k][ocg * 8 + o];
#pragma unroll
                for (int j = 0; j < 8; ++j) ireg[j] = sIn[ic][prow + ky][pcol + kx + j];
#pragma unroll
                for (int o = 0; o < 8; ++o)
#pragma unroll
                    for (int j = 0; j < 8; ++j)
                        acc[o][j] = fmaf(wreg[o], ireg[j], acc[o][j]);
            }
        }
    }

    // BN (inference) + ReLU epilogue
    const int y = ty0 + prow;
    if (y < HH) {
#pragma unroll
        for (int o = 0; o < 8; ++o) {
            const int oc = ocg * 8 + o;
            const float gamma = bnp[oc];
            const float beta  = bnp[64 + oc];
            const float mean  = bnp[128 + oc];
            const float var   = bnp[192 + oc];
            const float scale = gamma * rsqrtf(var + 1e-5f);
            float* orow = outp + (size_t)oc * HW + (size_t)y * WW;
#pragma unroll
            for (int j = 0; j < 8; ++j) {
                const int x = tx0 + pcol + j;
                if (x < WW) {
                    float v = (acc[o][j] - mean) * scale + beta;
                    orow[x] = fmaxf(v, 0.f);
                }
            }
        }
    }
}

// ---------------------------------------------------------------------------
// conv3x3 (64 -> 3) + bias, channel-select concat into head_out region.
// Block 256 = 16x16 pixels, 3 accumulators/thread. grid.z = b.
// ---------------------------------------------------------------------------
__global__ __launch_bounds__(256)
void conv2_kernel(const float* __restrict__ w2,
                  const float* __restrict__ b2,
                  float* __restrict__ out,
                  int head)
{
    const int b = blockIdx.z;
    const float* img = g_h + (size_t)b * 64 * HW;

    __shared__ float sW2[3 * 64 * 9];   // 1728
    __shared__ float sIn[8][18][21];

    const int tid = threadIdx.x;
    for (int e = tid; e < 1728; e += 256)
        sW2[e] = w2[(size_t)head * 1728 + e];

    const int ry = tid >> 4;
    const int rx = tid & 15;
    const int ty0 = blockIdx.y * 16;
    const int tx0 = blockIdx.x * 16;

    float a0 = 0.f, a1 = 0.f, a2 = 0.f;

    for (int ic0 = 0; ic0 < 64; ic0 += 8) {
        __syncthreads();
        for (int e = tid; e < 8 * 18 * 18; e += 256) {
            int ic = e / 324;
            int r  = (e % 324) / 18;
            int c  = e % 18;
            int gy = ty0 - 1 + r;
            int gx = tx0 - 1 + c;
            float v = 0.f;
            if ((unsigned)gy < HH && (unsigned)gx < WW)
                v = img[(size_t)(ic0 + ic) * HW + gy * WW + gx];
            sIn[ic][r][c] = v;
        }
        __syncthreads();

#pragma unroll 1
        for (int ic = 0; ic < 8; ++ic) {
#pragma unroll
            for (int k = 0; k < 9; ++k) {
                const int ky = k / 3, kx = k % 3;
                const float iv = sIn[ic][ry + ky][rx + kx];
                const int wb = (ic0 + ic) * 9 + k;
                a0 = fmaf(sW2[wb], iv, a0);
                a1 = fmaf(sW2[576 + wb], iv, a1);
                a2 = fmaf(sW2[1152 + wb], iv, a2);
            }
        }
    }

    const int y = ty0 + ry;
    const int x = tx0 + rx;
    if (y < HH && x < WW) {
        float av[3];
        av[0] = a0 + b2[head * 3 + 0];
        av[1] = a1 + b2[head * 3 + 1];
        av[2] = a2 + b2[head * 3 + 2];
        const int offc[6] = {0, 2, 3, 6, 8, 9};
        const int nch[6]  = {2, 1, 3, 2, 1, 3};
        for (int o = 0; o < nch[head]; ++o)
            out[OFF_HEAD + ((size_t)b * 12 + offc[head] + o) * HW + (size_t)y * WW + x] = av[o];
    }
}

// ---------------------------------------------------------------------------
// zero heatmap + target_boxes + inds + mask regions
// ---------------------------------------------------------------------------
__global__ void zero_tail_kernel(float* __restrict__ out)
{
    const int n = OUT_TOTAL - OFF_HM;
    int i = blockIdx.x * blockDim.x + threadIdx.x;
    if (i < n) out[OFF_HM + i] = 0.f;
}

// ---------------------------------------------------------------------------
// target assignment: one thread per (b, m) gt box.
// ---------------------------------------------------------------------------
__global__ void assign_kernel(const float* __restrict__ gt, float* __restrict__ out)
{
    const int t = blockIdx.x * blockDim.x + threadIdx.x;
    if (t >= BB * MM) return;
    const int b = t / MM;
    const int m = t % MM;
    const float* gb = gt + (size_t)(b * MM + m) * 8;

    const float x  = gb[0], y  = gb[1], zc = gb[2];
    const float dx = gb[3], dy = gb[4], dz = gb[5];
    const float hd = gb[6];
    const int   cls = (int)gb[7];

    const bool valid = (dx > 0.f) && (dy > 0.f);
    const float vf = valid ? 1.f : 0.f;

    float cx = (x - (-75.2f)) / 0.1f / 8.0f;
    cx = fminf(fmaxf(cx, 0.f), (float)WW - 0.5f);
    float cy = (y - (-75.2f)) / 0.1f / 8.0f;
    cy = fminf(fmaxf(cy, 0.f), (float)HH - 0.5f);
    const int cxi = (int)floorf(cx);
    const int cyi = (int)floorf(cy);

    const float dxp = dx / 0.1f / 8.0f;
    const float dyp = dy / 0.1f / 8.0f;

    // gaussian_radius(height=dxp, width=dyp, overlap=0.1)
    const float ov = 0.1f;
    const float hgt = dxp, wdt = dyp;
    const float b1 = hgt + wdt;
    const float c1 = wdt * hgt * (1.f - ov) / (1.f + ov);
    const float sq1 = sqrtf(fmaxf(b1 * b1 - 4.f * c1, 0.f));
    const float r1 = (b1 + sq1) * 0.5f;
    const float b2v = 2.f * (hgt + wdt);
    const float c2 = (1.f - ov) * wdt * hgt;
    const float sq2 = sqrtf(fmaxf(b2v * b2v - 16.f * c2, 0.f));
    const float r2 = (b2v + sq2) * 0.5f;
    const float a3 = 4.f * ov;
    const float b3 = -2.f * ov * (hgt + wdt);
    const float c3 = (ov - 1.f) * wdt * hgt;
    const float sq3 = sqrtf(fmaxf(b3 * b3 - 4.f * a3 * c3, 0.f));
    const float r3 = (b3 + sq3) * 0.5f;

    float r = fminf(fminf(r1, r2), r3);
    r = fmaxf(floorf(r), 2.0f);
    const float sigma = (2.f * r + 1.f) / 6.f;
    const float inv2s2 = 1.f / (2.f * sigma * sigma);

    // target_boxes / inds / mask
    float* tb = out + OFF_TB + (size_t)(b * NMAX + m) * 8;
    tb[0] = (cx - (float)cxi) * vf;
    tb[1] = (cy - (float)cyi) * vf;
    tb[2] = zc * vf;
    tb[3] = logf(dx) * vf;
    tb[4] = logf(dy) * vf;
    tb[5] = logf(dz) * vf;
    tb[6] = cosf(hd) * vf;
    tb[7] = sinf(hd) * vf;
    out[OFF_IND + b * NMAX + m]  = (float)((cyi * WW + cxi) * (valid ? 1 : 0));
    out[OFF_MASK + b * NMAX + m] = vf;

    if (!valid || cls < 1 || cls > 3) return;

    // gaussian max-splat into heatmap channel (cls-1)
    float* hm = out + OFF_HM + ((size_t)(b * 3 + (cls - 1))) * HW;
    const int ir = (int)r;
    for (int oy = -ir; oy <= ir; ++oy) {
        const int py = cyi + oy;
        if ((unsigned)py >= HH) continue;
        for (int ox = -ir; ox <= ir; ++ox) {
            const int px = cxi + ox;
            if ((unsigned)px >= WW) continue;
            const float g = expf(-(float)(oy * oy + ox * ox) * inv2s2);
            atomicMax((int*)&hm[(size_t)py * WW + px], __float_as_int(g));
        }
    }
}

// ---------------------------------------------------------------------------
extern "C" void kernel_launch(void* const* d_in, const int* in_sizes, int n_in,
                              void* d_out, int out_size)
{
    const float* sf       = (const float*)d_in[0];  // spatial_features [4,512,188,188]
    const float* gt       = (const float*)d_in[1];  // gt_boxes [4,200,8]
    const float* w_shared = (const float*)d_in[2];  // [64,512,3,3]
    const float* bn_sh    = (const float*)d_in[3];  // [4,64]
    const float* w1       = (const float*)d_in[4];  // [6,64,64,3,3]
    const float* bnh      = (const float*)d_in[5];  // [6,4,64]
    const float* w2       = (const float*)d_in[6];  // [6,3,64,3,3]
    const float* b2       = (const float*)d_in[7];  // [6,3]
    float* out = (float*)d_out;

    (void)in_sizes; (void)n_in; (void)out_size;

    // zero heatmap/targets, then splat (ordering via default stream)
    {
        const int n = OUT_TOTAL - OFF_HM;
        zero_tail_kernel<<<(n + 255) / 256, 256>>>(out);
    }
    assign_kernel<<<(BB * MM + 255) / 256, 256>>>(gt, out);

    // shared conv 512 -> 64 (+BN+ReLU)
    conv_bn_relu<512, false><<<dim3(12, 12, 4), 256>>>(sf, w_shared, bn_sh, 0);

    // per head: conv1 64 -> 64 (+BN+ReLU) into reused g_h, then conv2 64 -> 3
    for (int head = 0; head < 6; ++head) {
        conv_bn_relu<64, true><<<dim3(12, 12, 4), 256>>>(nullptr, w1, bnh, head);
        conv2_kernel<<<dim3(12, 12, 4), 256>>>(w2, b2, out, head);
    }
}

// round 4
// speedup vs baseline: 1.1272x; 1.1247x over previous
#include <cuda_runtime.h>
#include <math.h>

// ---------------------------------------------------------------------------
// CenterHead fp32. Round 4: vectorized smem loads + sliding-window conv inner
// loops; warp-uniform broadcast weight reads; heads re-batched into one launch.
// ---------------------------------------------------------------------------

#define HH 188
#define WW 188
#define HW (188*188)
#define BB 4
#define MM 200
#define NMAX 500

// output region offsets (float32 elements)
#define OFF_HEAD 0
#define OFF_HM   (4*12*HW)
#define OFF_TB   (OFF_HM + 4*3*HW)
#define OFF_IND  (OFF_TB + 4*NMAX*8)
#define OFF_MASK (OFF_IND + 4*NMAX)
#define OUT_TOTAL (OFF_MASK + 4*NMAX)

// scratch (static device arrays: allocation-free contract)
__device__ float g_shared_feat[4 * 64 * HW];   // [b][oc][h][w]    ~36 MB
__device__ float g_h[24 * 64 * HW];            // [head*4+b][oc][h][w] ~217 MB

// ---------------------------------------------------------------------------
// conv3x3 + BN + ReLU.  Block=256, tile 16x16 px x 64 oc.
// Thread = 8 oc x 8 px.  warp id == oc-group -> weight LDS are broadcasts.
// Input row of 10 floats loaded vectorized, reused across kx (sliding window).
// ---------------------------------------------------------------------------
template<int CIN, bool MULTI>
__global__ __launch_bounds__(256, 2)
void conv_bn_relu(const float* __restrict__ gin,
                  const float* __restrict__ wt,
                  const float* __restrict__ bn)
{
    const int z    = blockIdx.z;
    const int head = MULTI ? (z >> 2) : 0;
    const int b    = MULTI ? (z & 3)  : z;

    const float* img  = (MULTI ? g_shared_feat : gin) + (size_t)b * CIN * HW;
    float*       outp = (MULTI ? g_h : g_shared_feat) + (size_t)z * 64 * HW;
    const float* w    = wt + (size_t)head * 64 * CIN * 9;
    const float* bnp  = bn + head * 256;

    __shared__ float sIn[8][18][20];   // stride 20 floats = 80B (16B aligned)
    __shared__ float sW[8][9][64];     // [ic][k][oc]

    const int tid  = threadIdx.x;
    const int ocg  = tid >> 5;            // warp id == oc group (broadcast reads)
    const int pg   = tid & 31;
    const int prow = pg >> 1;             // 0..15
    const int pcol = (pg & 1) << 3;       // 0 or 8

    const int ty0 = blockIdx.y * 16;
    const int tx0 = blockIdx.x * 16;

    float acc[8][8];
#pragma unroll
    for (int o = 0; o < 8; ++o)
#pragma unroll
        for (int j = 0; j < 8; ++j) acc[o][j] = 0.f;

#pragma unroll 1
    for (int ic0 = 0; ic0 < CIN; ic0 += 8) {
        __syncthreads();
        // input tile 8 x 18 x 18 (halo)
        for (int e = tid; e < 8 * 18 * 18; e += 256) {
            int ic = e / 324;
            int r  = (e % 324) / 18;
            int c  = e % 18;
            int gy = ty0 - 1 + r;
            int gx = tx0 - 1 + c;
            float v = 0.f;
            if ((unsigned)gy < HH && (unsigned)gx < WW)
                v = img[(size_t)(ic0 + ic) * HW + gy * WW + gx];
            sIn[ic][r][c] = v;
        }
        // weights 8 x 9 x 64
        for (int e = tid; e < 72 * 64; e += 256) {
            int oc  = e & 63;
            int ick = e >> 6;                 // ic*9 + k
            sW[0][ick][oc] = w[(size_t)oc * CIN * 9 + ic0 * 9 + ick];
        }
        __syncthreads();

#pragma unroll 1
        for (int ic = 0; ic < 8; ++ic) {
#pragma unroll
            for (int ky = 0; ky < 3; ++ky) {
                const float* rp = &sIn[ic][prow + ky][pcol];
                float4 v0 = *(const float4*)rp;
                float4 v1 = *(const float4*)(rp + 4);
                float2 v2 = *(const float2*)(rp + 8);
                float rowv[10] = { v0.x, v0.y, v0.z, v0.w,
                                   v1.x, v1.y, v1.z, v1.w,
                                   v2.x, v2.y };
#pragma unroll
                for (int kx = 0; kx < 3; ++kx) {
                    const float* wp = &sW[ic][ky * 3 + kx][ocg * 8];
                    float4 w0 = *(const float4*)wp;       // broadcast
                    float4 w1 = *(const float4*)(wp + 4); // broadcast
                    float wv[8] = { w0.x, w0.y, w0.z, w0.w,
                                    w1.x, w1.y, w1.z, w1.w };
#pragma unroll
                    for (int o = 0; o < 8; ++o)
#pragma unroll
                        for (int j = 0; j < 8; ++j)
                            acc[o][j] = fmaf(wv[o], rowv[kx + j], acc[o][j]);
                }
            }
        }
    }

    // BN + ReLU epilogue
    const int y = ty0 + prow;
    if (y < HH) {
#pragma unroll
        for (int o = 0; o < 8; ++o) {
            const int oc = ocg * 8 + o;
            const float scale = bnp[oc] * rsqrtf(bnp[192 + oc] + 1e-5f);
            const float mean  = bnp[128 + oc];
            const float beta  = bnp[64 + oc];
            float* orow = outp + (size_t)oc * HW + (size_t)y * WW;
#pragma unroll
            for (int j = 0; j < 8; ++j) {
                const int x = tx0 + pcol + j;
                if (x < WW)
                    orow[x] = fmaxf((acc[o][j] - mean) * scale + beta, 0.f);
            }
        }
    }
}

// ---------------------------------------------------------------------------
// conv3x3 (64 -> 3) + bias, channel-select concat.
// Block=128, tile 32x32; thread = 8 px x 3 oc, sliding window.
// ---------------------------------------------------------------------------
__global__ __launch_bounds__(128)
void conv2_kernel(const float* __restrict__ w2,
                  const float* __restrict__ b2,
                  float* __restrict__ out)
{
    const int z    = blockIdx.z;
    const int head = z >> 2;
    const int b    = z & 3;
    const float* img = g_h + (size_t)z * 64 * HW;

    __shared__ float sW2[1728];        // [oc][ic][k]
    __shared__ float sK[4][34][36];    // stride 36 floats = 144B (16B aligned)

    const int tid = threadIdx.x;
    for (int e = tid; e < 1728; e += 128)
        sW2[e] = w2[(size_t)head * 1728 + e];

    const int row = tid >> 2;          // 0..31
    const int seg = (tid & 3) << 3;    // 0,8,16,24
    const int ty0 = blockIdx.y * 32;
    const int tx0 = blockIdx.x * 32;

    float acc[3][8];
#pragma unroll
    for (int o = 0; o < 3; ++o)
#pragma unroll
        for (int j = 0; j < 8; ++j) acc[o][j] = 0.f;

#pragma unroll 1
    for (int ic0 = 0; ic0 < 64; ic0 += 4) {
        __syncthreads();
        for (int e = tid; e < 4 * 34 * 34; e += 128) {
            int ic = e / 1156;
            int r  = (e % 1156) / 34;
            int c  = e % 34;
            int gy = ty0 - 1 + r;
            int gx = tx0 - 1 + c;
            float v = 0.f;
            if ((unsigned)gy < HH && (unsigned)gx < WW)
                v = img[(size_t)(ic0 + ic) * HW + gy * WW + gx];
            sK[ic][r][c] = v;
        }
        __syncthreads();

#pragma unroll 1
        for (int ic = 0; ic < 4; ++ic) {
#pragma unroll
            for (int ky = 0; ky < 3; ++ky) {
                const float* rp = &sK[ic][row + ky][seg];
                float4 v0 = *(const float4*)rp;
                float4 v1 = *(const float4*)(rp + 4);
                float2 v2 = *(const float2*)(rp + 8);
                float rowv[10] = { v0.x, v0.y, v0.z, v0.w,
                                   v1.x, v1.y, v1.z, v1.w,
                                   v2.x, v2.y };
#pragma unroll
                for (int kx = 0; kx < 3; ++kx) {
                    const int wb = (ic0 + ic) * 9 + ky * 3 + kx;
                    const float w0 = sW2[wb];          // uniform broadcast
                    const float w1 = sW2[576 + wb];
                    const float wv2 = sW2[1152 + wb];
#pragma unroll
                    for (int j = 0; j < 8; ++j) {
                        acc[0][j] = fmaf(w0,  rowv[kx + j], acc[0][j]);
                        acc[1][j] = fmaf(w1,  rowv[kx + j], acc[1][j]);
                        acc[2][j] = fmaf(wv2, rowv[kx + j], acc[2][j]);
                    }
                }
            }
        }
    }

    const int y = ty0 + row;
    if (y < HH) {
        const int offc[6] = {0, 2, 3, 6, 8, 9};
        const int nch[6]  = {2, 1, 3, 2, 1, 3};
        for (int o = 0; o < nch[head]; ++o) {
            const float bias = b2[head * 3 + o];
            float* orow = out + OFF_HEAD +
                ((size_t)b * 12 + offc[head] + o) * HW + (size_t)y * WW;
#pragma unroll
            for (int j = 0; j < 8; ++j) {
                const int x = tx0 + seg + j;
                if (x < WW) orow[x] = acc[o][j] + bias;
            }
        }
    }
}

// ---------------------------------------------------------------------------
__global__ void zero_tail_kernel(float* __restrict__ out)
{
    const int n = OUT_TOTAL - OFF_HM;
    int i = blockIdx.x * blockDim.x + threadIdx.x;
    if (i < n) out[OFF_HM + i] = 0.f;
}

// ---------------------------------------------------------------------------
// target assignment: one thread per (b, m) gt box.
// ---------------------------------------------------------------------------
__global__ void assign_kernel(const float* __restrict__ gt, float* __restrict__ out)
{
    const int t = blockIdx.x * blockDim.x + threadIdx.x;
    if (t >= BB * MM) return;
    const int b = t / MM;
    const int m = t % MM;
    const float* gb = gt + (size_t)(b * MM + m) * 8;

    const float x  = gb[0], y  = gb[1], zc = gb[2];
    const float dx = gb[3], dy = gb[4], dz = gb[5];
    const float hd = gb[6];
    const int   cls = (int)gb[7];

    const bool valid = (dx > 0.f) && (dy > 0.f);
    const float vf = valid ? 1.f : 0.f;

    float cx = (x + 75.2f) / 0.1f / 8.0f;
    cx = fminf(fmaxf(cx, 0.f), (float)WW - 0.5f);
    float cy = (y + 75.2f) / 0.1f / 8.0f;
    cy = fminf(fmaxf(cy, 0.f), (float)HH - 0.5f);
    const int cxi = (int)floorf(cx);
    const int cyi = (int)floorf(cy);

    const float dxp = dx / 0.1f / 8.0f;
    const float dyp = dy / 0.1f / 8.0f;

    const float ov = 0.1f;
    const float hgt = dxp, wdt = dyp;
    const float b1 = hgt + wdt;
    const float c1 = wdt * hgt * (1.f - ov) / (1.f + ov);
    const float sq1 = sqrtf(fmaxf(b1 * b1 - 4.f * c1, 0.f));
    const float r1 = (b1 + sq1) * 0.5f;
    const float b2v = 2.f * (hgt + wdt);
    const float c2 = (1.f - ov) * wdt * hgt;
    const float sq2 = sqrtf(fmaxf(b2v * b2v - 16.f * c2, 0.f));
    const float r2 = (b2v + sq2) * 0.5f;
    const float a3 = 4.f * ov;
    const float b3 = -2.f * ov * (hgt + wdt);
    const float c3 = (ov - 1.f) * wdt * hgt;
    const float sq3 = sqrtf(fmaxf(b3 * b3 - 4.f * a3 * c3, 0.f));
    const float r3 = (b3 + sq3) * 0.5f;

    float r = fminf(fminf(r1, r2), r3);
    r = fmaxf(floorf(r), 2.0f);
    const float sigma = (2.f * r + 1.f) / 6.f;
    const float inv2s2 = 1.f / (2.f * sigma * sigma);

    float* tb = out + OFF_TB + (size_t)(b * NMAX + m) * 8;
    tb[0] = (cx - (float)cxi) * vf;
    tb[1] = (cy - (float)cyi) * vf;
    tb[2] = zc * vf;
    tb[3] = logf(dx) * vf;
    tb[4] = logf(dy) * vf;
    tb[5] = logf(dz) * vf;
    tb[6] = cosf(hd) * vf;
    tb[7] = sinf(hd) * vf;
    out[OFF_IND + b * NMAX + m]  = (float)((cyi * WW + cxi) * (valid ? 1 : 0));
    out[OFF_MASK + b * NMAX + m] = vf;

    if (!valid || cls < 1 || cls > 3) return;

    float* hm = out + OFF_HM + ((size_t)(b * 3 + (cls - 1))) * HW;
    const int ir = (int)r;
    for (int oy = -ir; oy <= ir; ++oy) {
        const int py = cyi + oy;
        if ((unsigned)py >= HH) continue;
        for (int ox = -ir; ox <= ir; ++ox) {
            const int px = cxi + ox;
            if ((unsigned)px >= WW) continue;
            const float g = expf(-(float)(oy * oy + ox * ox) * inv2s2);
            atomicMax((int*)&hm[(size_t)py * WW + px], __float_as_int(g));
        }
    }
}

// ---------------------------------------------------------------------------
extern "C" void kernel_launch(void* const* d_in, const int* in_sizes, int n_in,
                              void* d_out, int out_size)
{
    const float* sf       = (const float*)d_in[0];
    const float* gt       = (const float*)d_in[1];
    const float* w_shared = (const float*)d_in[2];
    const float* bn_sh    = (const float*)d_in[3];
    const float* w1       = (const float*)d_in[4];
    const float* bnh      = (const float*)d_in[5];
    const float* w2       = (const float*)d_in[6];
    const float* b2       = (const float*)d_in[7];
    float* out = (float*)d_out;

    (void)in_sizes; (void)n_in; (void)out_size;

    {
        const int n = OUT_TOTAL - OFF_HM;
        zero_tail_kernel<<<(n + 255) / 256, 256>>>(out);
    }
    assign_kernel<<<(BB * MM + 255) / 256, 256>>>(gt, out);

    // shared conv 512 -> 64 (+BN+ReLU)
    conv_bn_relu<512, false><<<dim3(12, 12, 4), 256>>>(sf, w_shared, bn_sh);

    // six head conv1 64 -> 64 (+BN+ReLU), all heads in one launch
    conv_bn_relu<64, true><<<dim3(12, 12, 24), 256>>>(nullptr, w1, bnh);

    // six head conv2 64 -> 3 (+bias) with channel-select concat
    conv2_kernel<<<dim3(6, 6, 24), 128>>>(w2, b2, out);
}

// round 5
// speedup vs baseline: 1.1285x; 1.0012x over previous
#include <cuda_runtime.h>
#include <math.h>

// ---------------------------------------------------------------------------
// CenterHead fp32. Round 4: vectorized smem loads + sliding-window conv inner
// loops; warp-uniform broadcast weight reads; heads re-batched into one launch.
// ---------------------------------------------------------------------------

#define HH 188
#define WW 188
#define HW (188*188)
#define BB 4
#define MM 200
#define NMAX 500

// output region offsets (float32 elements)
#define OFF_HEAD 0
#define OFF_HM   (4*12*HW)
#define OFF_TB   (OFF_HM + 4*3*HW)
#define OFF_IND  (OFF_TB + 4*NMAX*8)
#define OFF_MASK (OFF_IND + 4*NMAX)
#define OUT_TOTAL (OFF_MASK + 4*NMAX)

// scratch (static device arrays: allocation-free contract)
__device__ float g_shared_feat[4 * 64 * HW];   // [b][oc][h][w]    ~36 MB
__device__ float g_h[24 * 64 * HW];            // [head*4+b][oc][h][w] ~217 MB

// ---------------------------------------------------------------------------
// conv3x3 + BN + ReLU.  Block=256, tile 16x16 px x 64 oc.
// Thread = 8 oc x 8 px.  warp id == oc-group -> weight LDS are broadcasts.
// Input row of 10 floats loaded vectorized, reused across kx (sliding window).
// ---------------------------------------------------------------------------
template<int CIN, bool MULTI>
__global__ __launch_bounds__(256, 2)
void conv_bn_relu(const float* __restrict__ gin,
                  const float* __restrict__ wt,
                  const float* __restrict__ bn)
{
    const int z    = blockIdx.z;
    const int head = MULTI ? (z >> 2) : 0;
    const int b    = MULTI ? (z & 3)  : z;

    const float* img  = (MULTI ? g_shared_feat : gin) + (size_t)b * CIN * HW;
    float*       outp = (MULTI ? g_h : g_shared_feat) + (size_t)z * 64 * HW;
    const float* w    = wt + (size_t)head * 64 * CIN * 9;
    const float* bnp  = bn + head * 256;

    __shared__ float sIn[8][18][20];   // stride 20 floats = 80B (16B aligned)
    __shared__ float sW[8][9][64];     // [ic][k][oc]

    const int tid  = threadIdx.x;
    const int ocg  = tid >> 5;            // warp id == oc group (broadcast reads)
    const int pg   = tid & 31;
    const int prow = pg >> 1;             // 0..15
    const int pcol = (pg & 1) << 3;       // 0 or 8

    const int ty0 = blockIdx.y * 16;
    const int tx0 = blockIdx.x * 16;

    float acc[8][8];
#pragma unroll
    for (int o = 0; o < 8; ++o)
#pragma unroll
        for (int j = 0; j < 8; ++j) acc[o][j] = 0.f;

#pragma unroll 1
    for (int ic0 = 0; ic0 < CIN; ic0 += 8) {
        __syncthreads();
        // input tile 8 x 18 x 18 (halo)
        for (int e = tid; e < 8 * 18 * 18; e += 256) {
            int ic = e / 324;
            int r  = (e % 324) / 18;
            int c  = e % 18;
            int gy = ty0 - 1 + r;
            int gx = tx0 - 1 + c;
            float v = 0.f;
            if ((unsigned)gy < HH && (unsigned)gx < WW)
                v = img[(size_t)(ic0 + ic) * HW + gy * WW + gx];
            sIn[ic][r][c] = v;
        }
        // weights 8 x 9 x 64
        for (int e = tid; e < 72 * 64; e += 256) {
            int oc  = e & 63;
            int ick = e >> 6;                 // ic*9 + k
            sW[0][ick][oc] = w[(size_t)oc * CIN * 9 + ic0 * 9 + ick];
        }
        __syncthreads();

#pragma unroll 1
        for (int ic = 0; ic < 8; ++ic) {
#pragma unroll
            for (int ky = 0; ky < 3; ++ky) {
                const float* rp = &sIn[ic][prow + ky][pcol];
                float4 v0 = *(const float4*)rp;
                float4 v1 = *(const float4*)(rp + 4);
                float2 v2 = *(const float2*)(rp + 8);
                float rowv[10] = { v0.x, v0.y, v0.z, v0.w,
                                   v1.x, v1.y, v1.z, v1.w,
                                   v2.x, v2.y };
#pragma unroll
                for (int kx = 0; kx < 3; ++kx) {
                    const float* wp = &sW[ic][ky * 3 + kx][ocg * 8];
                    float4 w0 = *(const float4*)wp;       // broadcast
                    float4 w1 = *(const float4*)(wp + 4); // broadcast
                    float wv[8] = { w0.x, w0.y, w0.z, w0.w,
                                    w1.x, w1.y, w1.z, w1.w };
#pragma unroll
                    for (int o = 0; o < 8; ++o)
#pragma unroll
                        for (int j = 0; j < 8; ++j)
                            acc[o][j] = fmaf(wv[o], rowv[kx + j], acc[o][j]);
                }
            }
        }
    }

    // BN + ReLU epilogue
    const int y = ty0 + prow;
    if (y < HH) {
#pragma unroll
        for (int o = 0; o < 8; ++o) {
            const int oc = ocg * 8 + o;
            const float scale = bnp[oc] * rsqrtf(bnp[192 + oc] + 1e-5f);
            const float mean  = bnp[128 + oc];
            const float beta  = bnp[64 + oc];
            float* orow = outp + (size_t)oc * HW + (size_t)y * WW;
#pragma unroll
            for (int j = 0; j < 8; ++j) {
                const int x = tx0 + pcol + j;
                if (x < WW)
                    orow[x] = fmaxf((acc[o][j] - mean) * scale + beta, 0.f);
            }
        }
    }
}

// ---------------------------------------------------------------------------
// conv3x3 (64 -> 3) + bias, channel-select concat.
// Block=128, tile 32x32; thread = 8 px x 3 oc, sliding window.
// ---------------------------------------------------------------------------
__global__ __launch_bounds__(128)
void conv2_kernel(const float* __restrict__ w2,
                  const float* __restrict__ b2,
                  float* __restrict__ out)
{
    const int z    = blockIdx.z;
    const int head = z >> 2;
    const int b    = z & 3;
    const float* img = g_h + (size_t)z * 64 * HW;

    __shared__ float sW2[1728];        // [oc][ic][k]
    __shared__ float sK[4][34][36];    // stride 36 floats = 144B (16B aligned)

    const int tid = threadIdx.x;
    for (int e = tid; e < 1728; e += 128)
        sW2[e] = w2[(size_t)head * 1728 + e];

    const int row = tid >> 2;          // 0..31
    const int seg = (tid & 3) << 3;    // 0,8,16,24
    const int ty0 = blockIdx.y * 32;
    const int tx0 = blockIdx.x * 32;

    float acc[3][8];
#pragma unroll
    for (int o = 0; o < 3; ++o)
#pragma unroll
        for (int j = 0; j < 8; ++j) acc[o][j] = 0.f;

#pragma unroll 1
    for (int ic0 = 0; ic0 < 64; ic0 += 4) {
        __syncthreads();
        for (int e = tid; e < 4 * 34 * 34; e += 128) {
            int ic = e / 1156;
            int r  = (e % 1156) / 34;
            int c  = e % 34;
            int gy = ty0 - 1 + r;
            int gx = tx0 - 1 + c;
            float v = 0.f;
            if ((unsigned)gy < HH && (unsigned)gx < WW)
                v = img[(size_t)(ic0 + ic) * HW + gy * WW + gx];
            sK[ic][r][c] = v;
        }
        __syncthreads();

#pragma unroll 1
        for (int ic = 0; ic < 4; ++ic) {
#pragma unroll
            for (int ky = 0; ky < 3; ++ky) {
                const float* rp = &sK[ic][row + ky][seg];
                float4 v0 = *(const float4*)rp;
                float4 v1 = *(const float4*)(rp + 4);
                float2 v2 = *(const float2*)(rp + 8);
                float rowv[10] = { v0.x, v0.y, v0.z, v0.w,
                                   v1.x, v1.y, v1.z, v1.w,
                                   v2.x, v2.y };
#pragma unroll
                for (int kx = 0; kx < 3; ++kx) {
                    const int wb = (ic0 + ic) * 9 + ky * 3 + kx;
                    const float w0 = sW2[wb];          // uniform broadcast
                    const float w1 = sW2[576 + wb];
                    const float wv2 = sW2[1152 + wb];
#pragma unroll
                    for (int j = 0; j < 8; ++j) {
                        acc[0][j] = fmaf(w0,  rowv[kx + j], acc[0][j]);
                        acc[1][j] = fmaf(w1,  rowv[kx + j], acc[1][j]);
                        acc[2][j] = fmaf(wv2, rowv[kx + j], acc[2][j]);
                    }
                }
            }
        }
    }

    const int y = ty0 + row;
    if (y < HH) {
        const int offc[6] = {0, 2, 3, 6, 8, 9};
        const int nch[6]  = {2, 1, 3, 2, 1, 3};
        for (int o = 0; o < nch[head]; ++o) {
            const float bias = b2[head * 3 + o];
            float* orow = out + OFF_HEAD +
                ((size_t)b * 12 + offc[head] + o) * HW + (size_t)y * WW;
#pragma unroll
            for (int j = 0; j < 8; ++j) {
                const int x = tx0 + seg + j;
                if (x < WW) orow[x] = acc[o][j] + bias;
            }
        }
    }
}

// ---------------------------------------------------------------------------
__global__ void zero_tail_kernel(float* __restrict__ out)
{
    const int n = OUT_TOTAL - OFF_HM;
    int i = blockIdx.x * blockDim.x + threadIdx.x;
    if (i < n) out[OFF_HM + i] = 0.f;
}

// ---------------------------------------------------------------------------
// target assignment: one thread per (b, m) gt box.
// ---------------------------------------------------------------------------
__global__ void assign_kernel(const float* __restrict__ gt, float* __restrict__ out)
{
    const int t = blockIdx.x * blockDim.x + threadIdx.x;
    if (t >= BB * MM) return;
    const int b = t / MM;
    const int m = t % MM;
    const float* gb = gt + (size_t)(b * MM + m) * 8;

    const float x  = gb[0], y  = gb[1], zc = gb[2];
    const float dx = gb[3], dy = gb[4], dz = gb[5];
    const float hd = gb[6];
    const int   cls = (int)gb[7];

    const bool valid = (dx > 0.f) && (dy > 0.f);
    const float vf = valid ? 1.f : 0.f;

    float cx = (x + 75.2f) / 0.1f / 8.0f;
    cx = fminf(fmaxf(cx, 0.f), (float)WW - 0.5f);
    float cy = (y + 75.2f) / 0.1f / 8.0f;
    cy = fminf(fmaxf(cy, 0.f), (float)HH - 0.5f);
    const int cxi = (int)floorf(cx);
    const int cyi = (int)floorf(cy);

    const float dxp = dx / 0.1f / 8.0f;
    const float dyp = dy / 0.1f / 8.0f;

    const float ov = 0.1f;
    const float hgt = dxp, wdt = dyp;
    const float b1 = hgt + wdt;
    const float c1 = wdt * hgt * (1.f - ov) / (1.f + ov);
    const float sq1 = sqrtf(fmaxf(b1 * b1 - 4.f * c1, 0.f));
    const float r1 = (b1 + sq1) * 0.5f;
    const float b2v = 2.f * (hgt + wdt);
    const float c2 = (1.f - ov) * wdt * hgt;
    const float sq2 = sqrtf(fmaxf(b2v * b2v - 16.f * c2, 0.f));
    const float r2 = (b2v + sq2) * 0.5f;
    const float a3 = 4.f * ov;
    const float b3 = -2.f * ov * (hgt + wdt);
    const float c3 = (ov - 1.f) * wdt * hgt;
    const float sq3 = sqrtf(fmaxf(b3 * b3 - 4.f * a3 * c3, 0.f));
    const float r3 = (b3 + sq3) * 0.5f;

    float r = fminf(fminf(r1, r2), r3);
    r = fmaxf(floorf(r), 2.0f);
    const float sigma = (2.f * r + 1.f) / 6.f;
    const float inv2s2 = 1.f / (2.f * sigma * sigma);

    float* tb = out + OFF_TB + (size_t)(b * NMAX + m) * 8;
    tb[0] = (cx - (float)cxi) * vf;
    tb[1] = (cy - (float)cyi) * vf;
    tb[2] = zc * vf;
    tb[3] = logf(dx) * vf;
    tb[4] = logf(dy) * vf;
    tb[5] = logf(dz) * vf;
    tb[6] = cosf(hd) * vf;
    tb[7] = sinf(hd) * vf;
    out[OFF_IND + b * NMAX + m]  = (float)((cyi * WW + cxi) * (valid ? 1 : 0));
    out[OFF_MASK + b * NMAX + m] = vf;

    if (!valid || cls < 1 || cls > 3) return;

    float* hm = out + OFF_HM + ((size_t)(b * 3 + (cls - 1))) * HW;
    const int ir = (int)r;
    for (int oy = -ir; oy <= ir; ++oy) {
        const int py = cyi + oy;
        if ((unsigned)py >= HH) continue;
        for (int ox = -ir; ox <= ir; ++ox) {
            const int px = cxi + ox;
            if ((unsigned)px >= WW) continue;
            const float g = expf(-(float)(oy * oy + ox * ox) * inv2s2);
            atomicMax((int*)&hm[(size_t)py * WW + px], __float_as_int(g));
        }
    }
}

// ---------------------------------------------------------------------------
extern "C" void kernel_launch(void* const* d_in, const int* in_sizes, int n_in,
                              void* d_out, int out_size)
{
    const float* sf       = (const float*)d_in[0];
    const float* gt       = (const float*)d_in[1];
    const float* w_shared = (const float*)d_in[2];
    const float* bn_sh    = (const float*)d_in[3];
    const float* w1       = (const float*)d_in[4];
    const float* bnh      = (const float*)d_in[5];
    const float* w2       = (const float*)d_in[6];
    const float* b2       = (const float*)d_in[7];
    float* out = (float*)d_out;

    (void)in_sizes; (void)n_in; (void)out_size;

    {
        const int n = OUT_TOTAL - OFF_HM;
        zero_tail_kernel<<<(n + 255) / 256, 256>>>(out);
    }
    assign_kernel<<<(BB * MM + 255) / 256, 256>>>(gt, out);

    // shared conv 512 -> 64 (+BN+ReLU)
    conv_bn_relu<512, false><<<dim3(12, 12, 4), 256>>>(sf, w_shared, bn_sh);

    // six head conv1 64 -> 64 (+BN+ReLU), all heads in one launch
    conv_bn_relu<64, true><<<dim3(12, 12, 24), 256>>>(nullptr, w1, bnh);

    // six head conv2 64 -> 3 (+bias) with channel-select concat
    conv2_kernel<<<dim3(6, 6, 24), 128>>>(w2, b2, out);
}